// round 4
// baseline (speedup 1.0000x reference)
#include <cuda_runtime.h>

#define BSZ  512
#define TLEN 512
#define IDIM 128
#define HDIM 50
#define ODIM 10
#define GDIM 200              // 4*H
#define BT   (BSZ * TLEN)     // 262144 rows

typedef unsigned long long u64;

// ---- scratch (device globals; no allocation allowed) ----
__device__ u64   g_Wt2[IDIM * GDIM];     // W_ih transposed, each value duplicated as f32x2
__device__ float g_bias[GDIM];           // b_ih + b_hh
__device__ float g_xp[BT * GDIM];        // x_proj: [row][g]

// ---- packed f32x2 helpers ----
__device__ __forceinline__ u64 pk2(float lo, float hi) {
    u64 d;
    asm("mov.b64 %0, {%1, %2};" : "=l"(d) : "f"(lo), "f"(hi));
    return d;
}
__device__ __forceinline__ void up2(u64 v, float& lo, float& hi) {
    asm("mov.b64 {%0, %1}, %2;" : "=f"(lo), "=f"(hi) : "l"(v));
}
__device__ __forceinline__ u64 ffma2(u64 a, u64 b, u64 c) {
    u64 d;
    asm("fma.rn.f32x2 %0, %1, %2, %3;" : "=l"(d) : "l"(a), "l"(b), "l"(c));
    return d;
}
__device__ __forceinline__ u64 fadd2(u64 a, u64 b) {
    u64 d;
    asm("add.rn.f32x2 %0, %1, %2;" : "=l"(d) : "l"(a), "l"(b));
    return d;
}
__device__ __forceinline__ float fast_sigmoid(float x) {
    return 1.f / (1.f + __expf(-x));
}

// ============================================================
// Kernel 0: W_ih -> g_Wt2 [k][g] duplicated pairs, bias sum
// ============================================================
__global__ void prep_w(const float* __restrict__ W_ih,
                       const float* __restrict__ b_ih,
                       const float* __restrict__ b_hh) {
    int t = threadIdx.x + blockIdx.x * 256;
    for (int idx = t; idx < IDIM * GDIM; idx += 256 * 32) {
        int g = idx / IDIM, k = idx % IDIM;
        float w = W_ih[idx];
        g_Wt2[k * GDIM + g] = pk2(w, w);
    }
    if (blockIdx.x == 0 && t < GDIM) g_bias[t] = b_ih[t] + b_hh[t];
}

// ============================================================
// Kernel 1: GEMM via packed f32x2, register-staged double buffer.
// g_xp[row][g] = sum_k x[row][k] * W[g][k] + bias[g]
// Reads x row-major directly; transposes into SMEM during staging.
// Block: 64 rows x 200 gates, 224 threads (tid<200 compute 8x8).
// ============================================================
#define MT 64
#define KT 16
#define XSW 68   // padded xs row width (floats); 16B-multiple, bank shift 4/k

__global__ __launch_bounds__(224, 2) void gemm_xproj(const float* __restrict__ x) {
    __shared__ float xs[KT][XSW];       // ~4.3 KB
    __shared__ u64   ws2[KT][GDIM];     // 25.6 KB
    const int tid = threadIdx.x;
    const int gr0 = blockIdx.x * MT;
    const int tm = tid & 7;
    const int tn = tid >> 3;
    const bool active = (tid < 200);

    u64 acc[4][8];
#pragma unroll
    for (int p = 0; p < 4; p++)
#pragma unroll
        for (int j = 0; j < 8; j++) acc[p][j] = 0ull;

    // staging registers
    float4 xr0, xr1;
    ulonglong2 wr[8];
    const int xrow0 = tid >> 2,        xc0i = tid & 3;          // idx = tid
    const int xrow1 = (tid + 224) >> 2, xc1i = (tid + 224) & 3; // idx = tid+224
    const bool hasx1 = (tid < 32);

    auto load_stage = [&](int kb) {
        xr0 = *(const float4*)&x[(size_t)(gr0 + xrow0) * IDIM + kb + xc0i * 4];
        if (hasx1)
            xr1 = *(const float4*)&x[(size_t)(gr0 + xrow1) * IDIM + kb + xc1i * 4];
#pragma unroll
        for (int u = 0; u < 7; u++) {
            int idx = tid + u * 224;
            int k = idx / 100, cc = idx % 100;
            wr[u] = *(const ulonglong2*)&g_Wt2[(kb + k) * GDIM + cc * 2];
        }
        if (tid < 32) {
            int idx = tid + 7 * 224;
            int k = idx / 100, cc = idx % 100;
            wr[7] = *(const ulonglong2*)&g_Wt2[(kb + k) * GDIM + cc * 2];
        }
    };
    auto store_stage = [&]() {
        xs[xc0i * 4 + 0][xrow0] = xr0.x;
        xs[xc0i * 4 + 1][xrow0] = xr0.y;
        xs[xc0i * 4 + 2][xrow0] = xr0.z;
        xs[xc0i * 4 + 3][xrow0] = xr0.w;
        if (hasx1) {
            xs[xc1i * 4 + 0][xrow1] = xr1.x;
            xs[xc1i * 4 + 1][xrow1] = xr1.y;
            xs[xc1i * 4 + 2][xrow1] = xr1.z;
            xs[xc1i * 4 + 3][xrow1] = xr1.w;
        }
#pragma unroll
        for (int u = 0; u < 7; u++) {
            int idx = tid + u * 224;
            int k = idx / 100, cc = idx % 100;
            *(ulonglong2*)&ws2[k][cc * 2] = wr[u];
        }
        if (tid < 32) {
            int idx = tid + 7 * 224;
            int k = idx / 100, cc = idx % 100;
            *(ulonglong2*)&ws2[k][cc * 2] = wr[7];
        }
    };

    load_stage(0);
    for (int it = 0; it < IDIM / KT; it++) {
        __syncthreads();
        store_stage();
        __syncthreads();
        if (it + 1 < IDIM / KT) load_stage((it + 1) * KT);   // overlap with compute

        if (active) {
#pragma unroll
            for (int k = 0; k < KT; k++) {
                ulonglong2 xa = *(const ulonglong2*)&xs[k][tm * 8];
                ulonglong2 xb = *(const ulonglong2*)&xs[k][tm * 8 + 4];
                u64 xp2[4] = {xa.x, xa.y, xb.x, xb.y};
                ulonglong2 w0 = *(const ulonglong2*)&ws2[k][tn * 8];
                ulonglong2 w1 = *(const ulonglong2*)&ws2[k][tn * 8 + 2];
                ulonglong2 w2 = *(const ulonglong2*)&ws2[k][tn * 8 + 4];
                ulonglong2 w3 = *(const ulonglong2*)&ws2[k][tn * 8 + 6];
                u64 wv[8] = {w0.x, w0.y, w1.x, w1.y, w2.x, w2.y, w3.x, w3.y};
#pragma unroll
                for (int p = 0; p < 4; p++)
#pragma unroll
                    for (int j = 0; j < 8; j++)
                        acc[p][j] = ffma2(xp2[p], wv[j], acc[p][j]);
            }
        }
    }

    if (active) {
        float bv[8];
#pragma unroll
        for (int j = 0; j < 8; j++) bv[j] = g_bias[tn * 8 + j];
#pragma unroll
        for (int p = 0; p < 4; p++) {
            float r0[8], r1[8];
#pragma unroll
            for (int j = 0; j < 8; j++) {
                float a, b;
                up2(acc[p][j], a, b);
                r0[j] = a + bv[j];
                r1[j] = b + bv[j];
            }
            int row0 = gr0 + tm * 8 + 2 * p;
            float* o0 = &g_xp[(size_t)row0 * GDIM + tn * 8];
            float* o1 = o0 + GDIM;
            *(float4*)o0       = make_float4(r0[0], r0[1], r0[2], r0[3]);
            *(float4*)(o0 + 4) = make_float4(r0[4], r0[5], r0[6], r0[7]);
            *(float4*)o1       = make_float4(r1[0], r1[1], r1[2], r1[3]);
            *(float4*)(o1 + 4) = make_float4(r1[4], r1[5], r1[6], r1[7]);
        }
    }
}

// ============================================================
// Kernel 2: LSTM recurrence + FC head. Split-K over hidden dim.
// Grid 256, block 448 = two 224-thread halves; each block owns
// 2 batches. Thread (half, g) computes a partial gate dot over
// j in [0,26) or [26,50). W_hh lives in SMEM as pre-duplicated
// f32x2 pairs (stride-25 ulonglong2 rows -> conflict-free).
// h interleaved float2 {b0,b1}; one FFMA2 = 2 MACs.
// ============================================================
#define LSTM_W2D_B   (GDIM * 25 * 16)                // 80000
#define LSTM_H_OFF   LSTM_W2D_B
#define LSTM_G_OFF   (LSTM_H_OFF + 52 * 8)           // 80416
#define LSTM_P_OFF   (LSTM_G_OFF + GDIM * 8)         // 82016
#define LSTM_SMEM    (LSTM_P_OFF + GDIM * 8)         // 83616

__global__ __launch_bounds__(448, 2) void lstm_rec(
    const float* __restrict__ W_hh, const float* __restrict__ W_fc,
    const float* __restrict__ b_fc, float* __restrict__ out)
{
    extern __shared__ char sm[];
    ulonglong2* w2d     = (ulonglong2*)sm;                 // [200][25] dup pairs
    float2*     h_sh    = (float2*)(sm + LSTM_H_OFF);      // [50] {b0,b1}
    float2*     gate_sh = (float2*)(sm + LSTM_G_OFF);      // [200]
    u64*        psum    = (u64*)(sm + LSTM_P_OFF);         // [200]

    const int tid  = threadIdx.x;
    const int half = tid / 224;          // warp 7 boundary
    const int g    = tid % 224;
    const int b0   = blockIdx.x * 2;
    const bool gate_active = (g < GDIM);

    // fill duplicated W_hh pairs: entry (gate gg, i) = {w[2i],w[2i]},{w[2i+1],w[2i+1]}
    for (int idx = tid; idx < GDIM * 25; idx += 448) {
        int gg = idx / 25, i = idx % 25;
        float w0 = W_hh[gg * HDIM + 2 * i];
        float w1 = W_hh[gg * HDIM + 2 * i + 1];
        ulonglong2 v;
        v.x = pk2(w0, w0);
        v.y = pk2(w1, w1);
        w2d[idx] = v;
    }
    if (tid < HDIM) h_sh[tid] = make_float2(0.f, 0.f);
    float c0 = 0.f, c1 = 0.f;

    const float* xp0 = g_xp + (size_t)b0 * (TLEN * GDIM);
    const float* xp1 = xp0 + (size_t)(TLEN * GDIM);
    float xc0 = 0.f, xc1 = 0.f;
    if (half == 0 && gate_active) { xc0 = xp0[g]; xc1 = xp1[g]; }
    const bool isg = (g >= 2 * HDIM && g < 3 * HDIM);
    const ulonglong2* wrow = w2d + g * 25 + (half ? 13 : 0);
    const float2* hbase = h_sh + (half ? 26 : 0);
    __syncthreads();

    for (int t = 0; t < TLEN; t++) {
        u64 s = 0ull;
        if (gate_active) {
            u64 acc[4];
            acc[0] = half == 0 ? pk2(xc0, xc1) : 0ull;
            acc[1] = acc[2] = acc[3] = 0ull;
            if (half == 0 && t + 1 < TLEN) {          // prefetch next x_proj
                xc0 = xp0[(t + 1) * GDIM + g];
                xc1 = xp1[(t + 1) * GDIM + g];
            }
            if (half == 0) {
#pragma unroll
                for (int i = 0; i < 13; i++) {         // j = 0..25
                    ulonglong2 hv = *(const ulonglong2*)(hbase + 2 * i);
                    ulonglong2 wv = wrow[i];
                    acc[(2 * i) & 3]     = ffma2(hv.x, wv.x, acc[(2 * i) & 3]);
                    acc[(2 * i + 1) & 3] = ffma2(hv.y, wv.y, acc[(2 * i + 1) & 3]);
                }
            } else {
#pragma unroll
                for (int i = 0; i < 12; i++) {         // j = 26..49
                    ulonglong2 hv = *(const ulonglong2*)(hbase + 2 * i);
                    ulonglong2 wv = wrow[i];
                    acc[(2 * i) & 3]     = ffma2(hv.x, wv.x, acc[(2 * i) & 3]);
                    acc[(2 * i + 1) & 3] = ffma2(hv.y, wv.y, acc[(2 * i + 1) & 3]);
                }
            }
            s = fadd2(fadd2(acc[0], acc[2]), fadd2(acc[1], acc[3]));
            if (half == 1) psum[g] = s;
        }
        __syncthreads();

        if (half == 0 && gate_active) {
            u64 tot = fadd2(s, psum[g]);
            float a0, a1;
            up2(tot, a0, a1);
            float z0 = isg ? (a0 + a0) : a0;
            float z1 = isg ? (a1 + a1) : a1;
            float s0 = fast_sigmoid(z0);
            float s1 = fast_sigmoid(z1);
            float r0 = isg ? (2.f * s0 - 1.f) : s0;
            float r1 = isg ? (2.f * s1 - 1.f) : s1;
            gate_sh[g] = make_float2(r0, r1);
        }
        __syncthreads();

        if (half == 1 && g < HDIM) {                   // c/h update
            float2 iv = gate_sh[g];
            float2 fv = gate_sh[g + HDIM];
            float2 gv = gate_sh[g + 2 * HDIM];
            float2 ov = gate_sh[g + 3 * HDIM];
            c0 = fmaf(fv.x, c0, iv.x * gv.x);
            c1 = fmaf(fv.y, c1, iv.y * gv.y);
            float th0 = 2.f * fast_sigmoid(c0 + c0) - 1.f;
            float th1 = 2.f * fast_sigmoid(c1 + c1) - 1.f;
            h_sh[g] = make_float2(ov.x * th0, ov.y * th1);
        }
        __syncthreads();
    }

    // FC head for both batches
    if (half == 0 && g < ODIM) {
        float a0 = b_fc[g], a1 = a0;
#pragma unroll
        for (int j = 0; j < HDIM; j++) {
            float2 h = h_sh[j];
            float w = W_fc[g * HDIM + j];
            a0 = fmaf(h.x, w, a0);
            a1 = fmaf(h.y, w, a1);
        }
        out[b0 * ODIM + g]       = a0;
        out[(b0 + 1) * ODIM + g] = a1;
    }
}

// ============================================================
// Launch
// ============================================================
extern "C" void kernel_launch(void* const* d_in, const int* in_sizes, int n_in,
                              void* d_out, int out_size) {
    const float* x    = (const float*)d_in[0];
    const float* W_ih = (const float*)d_in[1];
    const float* W_hh = (const float*)d_in[2];
    const float* b_ih = (const float*)d_in[3];
    const float* b_hh = (const float*)d_in[4];
    const float* W_fc = (const float*)d_in[5];
    const float* b_fc = (const float*)d_in[6];
    float* out = (float*)d_out;

    cudaFuncSetAttribute(lstm_rec, cudaFuncAttributeMaxDynamicSharedMemorySize,
                         LSTM_SMEM);

    prep_w<<<32, 256>>>(W_ih, b_ih, b_hh);
    gemm_xproj<<<BT / MT, 224>>>(x);
    lstm_rec<<<BSZ / 2, 448, LSTM_SMEM>>>(W_hh, W_fc, b_fc, out);
}

// round 5
// speedup vs baseline: 1.2252x; 1.2252x over previous
#include <cuda_runtime.h>

#define BSZ  512
#define TLEN 512
#define IDIM 128
#define HDIM 50
#define ODIM 10
#define GDIM 200              // 4*H
#define BT   (BSZ * TLEN)     // 262144 rows

typedef unsigned long long u64;

// ---- scratch (device globals; no allocation allowed) ----
__device__ float g_xT[IDIM * BT];        // x transposed: [k][row]
__device__ u64   g_Wt2[IDIM * GDIM];     // W_ih transposed, duplicated f32x2
__device__ float g_bias[GDIM];           // b_ih + b_hh
__device__ float g_xp[BT * GDIM];        // x_proj: [row][g]

// ---- packed f32x2 helpers ----
__device__ __forceinline__ u64 pk2(float lo, float hi) {
    u64 d;
    asm("mov.b64 %0, {%1, %2};" : "=l"(d) : "f"(lo), "f"(hi));
    return d;
}
__device__ __forceinline__ void up2(u64 v, float& lo, float& hi) {
    asm("mov.b64 {%0, %1}, %2;" : "=f"(lo), "=f"(hi) : "l"(v));
}
__device__ __forceinline__ u64 ffma2(u64 a, u64 b, u64 c) {
    u64 d;
    asm("fma.rn.f32x2 %0, %1, %2, %3;" : "=l"(d) : "l"(a), "l"(b), "l"(c));
    return d;
}
__device__ __forceinline__ u64 fadd2(u64 a, u64 b) {
    u64 d;
    asm("add.rn.f32x2 %0, %1, %2;" : "=l"(d) : "l"(a), "l"(b));
    return d;
}
__device__ __forceinline__ float fast_sigmoid(float x) {
    return 1.f / (1.f + __expf(-x));
}
// 16B async copy global->shared
__device__ __forceinline__ void cp16(void* smem, const void* gmem) {
    unsigned sa = (unsigned)__cvta_generic_to_shared(smem);
    asm volatile("cp.async.cg.shared.global [%0], [%1], 16;\n" :: "r"(sa), "l"(gmem));
}

// ============================================================
// Kernel 0: W_ih -> g_Wt2 [k][g] duplicated pairs, bias sum
// ============================================================
__global__ void prep_w(const float* __restrict__ W_ih,
                       const float* __restrict__ b_ih,
                       const float* __restrict__ b_hh) {
    int t = threadIdx.x + blockIdx.x * 256;
    for (int idx = t; idx < IDIM * GDIM; idx += 256 * 32) {
        int g = idx / IDIM, k = idx % IDIM;
        float w = W_ih[idx];
        g_Wt2[k * GDIM + g] = pk2(w, w);
    }
    if (blockIdx.x == 0 && t < GDIM) g_bias[t] = b_ih[t] + b_hh[t];
}

// ============================================================
// Kernel 1: transpose x [BT][128] -> g_xT [128][BT]
// ============================================================
__global__ void transpose_x(const float* __restrict__ x) {
    __shared__ float tile[32][33];
    int r0 = blockIdx.x * 32;
    int k0 = blockIdx.y * 32;
    int tx = threadIdx.x, ty = threadIdx.y;   // (32, 8)
#pragma unroll
    for (int i = 0; i < 32; i += 8)
        tile[ty + i][tx] = x[(r0 + ty + i) * IDIM + k0 + tx];
    __syncthreads();
#pragma unroll
    for (int i = 0; i < 32; i += 8)
        g_xT[(k0 + ty + i) * BT + r0 + tx] = tile[tx][ty + i];
}

// ============================================================
// Kernel 2: GEMM via packed f32x2, cp.async double-buffered.
// g_xp[row][g] = sum_k xT[k][row] * W[g][k] + bias[g]
// Block: 64 rows x 200 gates, 224 threads (tid<200 compute 8x8).
// One __syncthreads per K-tile; next tile loads overlap compute.
// ============================================================
#define MT 64
#define KT 16
#define XS_B (KT * MT * 4)          // 4096 per buffer
#define WS_B (KT * GDIM * 8)        // 25600 per buffer
#define GEMM_SMEM (2 * XS_B + 2 * WS_B)   // 59392

__global__ __launch_bounds__(224, 2) void gemm_xproj() {
    extern __shared__ char smraw[];
    float* xs_base = (float*)smraw;                  // [2][KT][MT]
    u64*   ws_base = (u64*)(smraw + 2 * XS_B);       // [2][KT][GDIM]
    const int tid = threadIdx.x;
    const int gr0 = blockIdx.x * MT;
    const int tm = tid & 7;
    const int tn = tid >> 3;
    const bool active = (tid < 200);

    u64 acc[4][8];
#pragma unroll
    for (int p = 0; p < 4; p++)
#pragma unroll
        for (int j = 0; j < 8; j++) acc[p][j] = 0ull;

    auto issue_tile = [&](int kb, int buf) {
        float* xsb = xs_base + buf * (KT * MT);
        u64*   wsb = ws_base + buf * (KT * GDIM);
        {   // x tile: 256 16B chunks (16 per k-row)
            int k = tid >> 4, c = tid & 15;
            cp16(&xsb[k * MT + c * 4], &g_xT[(size_t)(kb + k) * BT + gr0 + c * 4]);
            if (tid < 32) {
                int idx = tid + 224, k2 = idx >> 4, c2 = idx & 15;
                cp16(&xsb[k2 * MT + c2 * 4], &g_xT[(size_t)(kb + k2) * BT + gr0 + c2 * 4]);
            }
        }
        {   // W tile: 1600 16B chunks (100 per k-row)
#pragma unroll
            for (int u = 0; u < 7; u++) {
                int idx = tid + u * 224;
                int k = idx / 100, cc = idx % 100;
                cp16(&wsb[k * GDIM + cc * 2], &g_Wt2[(kb + k) * GDIM + cc * 2]);
            }
            if (tid < 32) {
                int idx = tid + 7 * 224;
                int k = idx / 100, cc = idx % 100;
                cp16(&wsb[k * GDIM + cc * 2], &g_Wt2[(kb + k) * GDIM + cc * 2]);
            }
        }
        asm volatile("cp.async.commit_group;\n" ::: "memory");
    };

    issue_tile(0, 0);
    int buf = 0;
    const int NTILES = IDIM / KT;
    for (int it = 0; it < NTILES; it++) {
        asm volatile("cp.async.wait_group 0;\n" ::: "memory");
        __syncthreads();                      // current tile visible to all
        if (it + 1 < NTILES) issue_tile((it + 1) * KT, buf ^ 1);

        const float* xsb = xs_base + buf * (KT * MT);
        const u64*   wsb = ws_base + buf * (KT * GDIM);
        if (active) {
#pragma unroll
            for (int k = 0; k < KT; k++) {
                ulonglong2 xa = *(const ulonglong2*)&xsb[k * MT + tm * 8];
                ulonglong2 xb = *(const ulonglong2*)&xsb[k * MT + tm * 8 + 4];
                u64 xp2[4] = {xa.x, xa.y, xb.x, xb.y};
                ulonglong2 w0 = *(const ulonglong2*)&wsb[k * GDIM + tn * 8];
                ulonglong2 w1 = *(const ulonglong2*)&wsb[k * GDIM + tn * 8 + 2];
                ulonglong2 w2 = *(const ulonglong2*)&wsb[k * GDIM + tn * 8 + 4];
                ulonglong2 w3 = *(const ulonglong2*)&wsb[k * GDIM + tn * 8 + 6];
                u64 wv[8] = {w0.x, w0.y, w1.x, w1.y, w2.x, w2.y, w3.x, w3.y};
#pragma unroll
                for (int p = 0; p < 4; p++)
#pragma unroll
                    for (int j = 0; j < 8; j++)
                        acc[p][j] = ffma2(xp2[p], wv[j], acc[p][j]);
            }
        }
        __syncthreads();                      // done reading buf before overwrite
        buf ^= 1;
    }

    if (active) {
        float bv[8];
#pragma unroll
        for (int j = 0; j < 8; j++) bv[j] = g_bias[tn * 8 + j];
#pragma unroll
        for (int p = 0; p < 4; p++) {
            float r0[8], r1[8];
#pragma unroll
            for (int j = 0; j < 8; j++) {
                float a, b;
                up2(acc[p][j], a, b);
                r0[j] = a + bv[j];
                r1[j] = b + bv[j];
            }
            int row0 = gr0 + tm * 8 + 2 * p;
            float* o0 = &g_xp[(size_t)row0 * GDIM + tn * 8];
            float* o1 = o0 + GDIM;
            *(float4*)o0       = make_float4(r0[0], r0[1], r0[2], r0[3]);
            *(float4*)(o0 + 4) = make_float4(r0[4], r0[5], r0[6], r0[7]);
            *(float4*)o1       = make_float4(r1[0], r1[1], r1[2], r1[3]);
            *(float4*)(o1 + 4) = make_float4(r1[4], r1[5], r1[6], r1[7]);
        }
    }
}

// ============================================================
// Kernel 3: LSTM recurrence + FC head, 4 batches per block.
// Grid 128 (<= 148 SMs: one block per SM, no wave imbalance).
// Thread g<200 owns gate g for 4 batches: weights as duplicated
// f32x2 in registers, h as float4 {b0,b1,b2,b3} in SMEM.
// One LDS.128 feeds two FFMA2s (4 MACs).
// ============================================================
__global__ __launch_bounds__(224) void lstm_rec(
    const float* __restrict__ W_hh, const float* __restrict__ W_fc,
    const float* __restrict__ b_fc, float* __restrict__ out)
{
    __shared__ alignas(16) float4 h4[HDIM];
    __shared__ alignas(16) float4 gate4[GDIM];
    const int b0 = blockIdx.x * 4;
    const int g = threadIdx.x;

    u64 w2[HDIM];
    if (g < GDIM) {
#pragma unroll
        for (int j = 0; j < HDIM; j++) {
            float w = W_hh[g * HDIM + j];
            w2[j] = pk2(w, w);
        }
    }
    if (g < HDIM) h4[g] = make_float4(0.f, 0.f, 0.f, 0.f);
    float c0 = 0.f, c1 = 0.f, c2 = 0.f, c3 = 0.f;

    const float* xp0 = g_xp + (size_t)(b0 + 0) * (TLEN * GDIM);
    const float* xp1 = g_xp + (size_t)(b0 + 1) * (TLEN * GDIM);
    const float* xp2 = g_xp + (size_t)(b0 + 2) * (TLEN * GDIM);
    const float* xp3 = g_xp + (size_t)(b0 + 3) * (TLEN * GDIM);
    float xc0 = 0.f, xc1 = 0.f, xc2 = 0.f, xc3 = 0.f;
    if (g < GDIM) { xc0 = xp0[g]; xc1 = xp1[g]; xc2 = xp2[g]; xc3 = xp3[g]; }
    const bool isg = (g >= 2 * HDIM && g < 3 * HDIM);   // tanh gate
    __syncthreads();

    for (int t = 0; t < TLEN; t++) {
        if (g < GDIM) {
            u64 aA = pk2(xc0, xc1), aB = 0ull;     // batches 0,1
            u64 bA = pk2(xc2, xc3), bB = 0ull;     // batches 2,3
            if (t + 1 < TLEN) {                    // prefetch next step
                int o = (t + 1) * GDIM + g;
                xc0 = xp0[o]; xc1 = xp1[o]; xc2 = xp2[o]; xc3 = xp3[o];
            }
#pragma unroll
            for (int j = 0; j < HDIM; j += 2) {
                ulonglong2 h0 = *(const ulonglong2*)&h4[j];     // {b0,b1},{b2,b3}
                ulonglong2 h1 = *(const ulonglong2*)&h4[j + 1];
                aA = ffma2(h0.x, w2[j],     aA);
                bA = ffma2(h0.y, w2[j],     bA);
                aB = ffma2(h1.x, w2[j + 1], aB);
                bB = ffma2(h1.y, w2[j + 1], bB);
            }
            float a0, a1, a2, a3;
            up2(fadd2(aA, aB), a0, a1);
            up2(fadd2(bA, bB), a2, a3);
            float r0, r1, r2, r3;
            if (isg) {
                r0 = 2.f * fast_sigmoid(a0 + a0) - 1.f;
                r1 = 2.f * fast_sigmoid(a1 + a1) - 1.f;
                r2 = 2.f * fast_sigmoid(a2 + a2) - 1.f;
                r3 = 2.f * fast_sigmoid(a3 + a3) - 1.f;
            } else {
                r0 = fast_sigmoid(a0);
                r1 = fast_sigmoid(a1);
                r2 = fast_sigmoid(a2);
                r3 = fast_sigmoid(a3);
            }
            gate4[g] = make_float4(r0, r1, r2, r3);
        }
        __syncthreads();
        if (g < HDIM) {
            float4 iv = gate4[g];
            float4 fv = gate4[g + HDIM];
            float4 gv = gate4[g + 2 * HDIM];
            float4 ov = gate4[g + 3 * HDIM];
            c0 = fmaf(fv.x, c0, iv.x * gv.x);
            c1 = fmaf(fv.y, c1, iv.y * gv.y);
            c2 = fmaf(fv.z, c2, iv.z * gv.z);
            c3 = fmaf(fv.w, c3, iv.w * gv.w);
            float t0 = 2.f * fast_sigmoid(c0 + c0) - 1.f;
            float t1 = 2.f * fast_sigmoid(c1 + c1) - 1.f;
            float t2 = 2.f * fast_sigmoid(c2 + c2) - 1.f;
            float t3 = 2.f * fast_sigmoid(c3 + c3) - 1.f;
            h4[g] = make_float4(ov.x * t0, ov.y * t1, ov.z * t2, ov.w * t3);
        }
        __syncthreads();
    }

    // FC head for 4 batches
    if (g < ODIM) {
        float a0 = b_fc[g], a1 = a0, a2 = a0, a3 = a0;
#pragma unroll
        for (int j = 0; j < HDIM; j++) {
            float4 h = h4[j];
            float w = W_fc[g * HDIM + j];
            a0 = fmaf(h.x, w, a0);
            a1 = fmaf(h.y, w, a1);
            a2 = fmaf(h.z, w, a2);
            a3 = fmaf(h.w, w, a3);
        }
        out[(b0 + 0) * ODIM + g] = a0;
        out[(b0 + 1) * ODIM + g] = a1;
        out[(b0 + 2) * ODIM + g] = a2;
        out[(b0 + 3) * ODIM + g] = a3;
    }
}

// ============================================================
// Launch
// ============================================================
extern "C" void kernel_launch(void* const* d_in, const int* in_sizes, int n_in,
                              void* d_out, int out_size) {
    const float* x    = (const float*)d_in[0];
    const float* W_ih = (const float*)d_in[1];
    const float* W_hh = (const float*)d_in[2];
    const float* b_ih = (const float*)d_in[3];
    const float* b_hh = (const float*)d_in[4];
    const float* W_fc = (const float*)d_in[5];
    const float* b_fc = (const float*)d_in[6];
    float* out = (float*)d_out;

    cudaFuncSetAttribute(gemm_xproj, cudaFuncAttributeMaxDynamicSharedMemorySize,
                         GEMM_SMEM);

    prep_w<<<32, 256>>>(W_ih, b_ih, b_hh);
    transpose_x<<<dim3(BT / 32, IDIM / 32), dim3(32, 8)>>>(x);
    gemm_xproj<<<BT / MT, 224, GEMM_SMEM>>>();
    lstm_rec<<<BSZ / 4, 224>>>(W_hh, W_fc, b_fc, out);
}

// round 6
// speedup vs baseline: 1.6486x; 1.3456x over previous
#include <cuda_runtime.h>

#define BSZ  512
#define TLEN 512
#define IDIM 128
#define HDIM 50
#define ODIM 10
#define GDIM 200              // 4*H
#define BT   (BSZ * TLEN)     // 262144 rows

typedef unsigned long long u64;

// ---- scratch (device globals; no allocation allowed) ----
__device__ float g_xT[IDIM * BT];        // x transposed: [k][row]
__device__ u64   g_Wt2[IDIM * GDIM];     // W_ih transposed, duplicated f32x2
__device__ float g_bias[GDIM];           // b_ih + b_hh
__device__ float g_xp[BT * GDIM];        // x_proj: [row][g]

// ---- packed f32x2 helpers ----
__device__ __forceinline__ u64 pk2(float lo, float hi) {
    u64 d;
    asm("mov.b64 %0, {%1, %2};" : "=l"(d) : "f"(lo), "f"(hi));
    return d;
}
__device__ __forceinline__ void up2(u64 v, float& lo, float& hi) {
    asm("mov.b64 {%0, %1}, %2;" : "=f"(lo), "=f"(hi) : "l"(v));
}
__device__ __forceinline__ u64 ffma2(u64 a, u64 b, u64 c) {
    u64 d;
    asm("fma.rn.f32x2 %0, %1, %2, %3;" : "=l"(d) : "l"(a), "l"(b), "l"(c));
    return d;
}
__device__ __forceinline__ u64 fadd2(u64 a, u64 b) {
    u64 d;
    asm("add.rn.f32x2 %0, %1, %2;" : "=l"(d) : "l"(a), "l"(b));
    return d;
}
__device__ __forceinline__ float fast_sigmoid(float x) {
    return 1.f / (1.f + __expf(-x));
}
// 16B async copy global->shared
__device__ __forceinline__ void cp16(void* smem, const void* gmem) {
    unsigned sa = (unsigned)__cvta_generic_to_shared(smem);
    asm volatile("cp.async.cg.shared.global [%0], [%1], 16;\n" :: "r"(sa), "l"(gmem));
}

// ============================================================
// Kernel 0: W_ih -> g_Wt2 [k][g] duplicated pairs, bias sum
// ============================================================
__global__ void prep_w(const float* __restrict__ W_ih,
                       const float* __restrict__ b_ih,
                       const float* __restrict__ b_hh) {
    int t = threadIdx.x + blockIdx.x * 256;
    for (int idx = t; idx < IDIM * GDIM; idx += 256 * 32) {
        int g = idx / IDIM, k = idx % IDIM;
        float w = W_ih[idx];
        g_Wt2[k * GDIM + g] = pk2(w, w);
    }
    if (blockIdx.x == 0 && t < GDIM) g_bias[t] = b_ih[t] + b_hh[t];
}

// ============================================================
// Kernel 1: transpose x [BT][128] -> g_xT [128][BT]
// ============================================================
__global__ void transpose_x(const float* __restrict__ x) {
    __shared__ float tile[32][33];
    int r0 = blockIdx.x * 32;
    int k0 = blockIdx.y * 32;
    int tx = threadIdx.x, ty = threadIdx.y;   // (32, 8)
#pragma unroll
    for (int i = 0; i < 32; i += 8)
        tile[ty + i][tx] = x[(r0 + ty + i) * IDIM + k0 + tx];
    __syncthreads();
#pragma unroll
    for (int i = 0; i < 32; i += 8)
        g_xT[(k0 + ty + i) * BT + r0 + tx] = tile[tx][ty + i];
}

// ============================================================
// Kernel 2: GEMM via packed f32x2, cp.async double-buffered.
// (unchanged from R5 — measured ~360us)
// ============================================================
#define MT 64
#define KT 16
#define XS_B (KT * MT * 4)          // 4096 per buffer
#define WS_B (KT * GDIM * 8)        // 25600 per buffer
#define GEMM_SMEM (2 * XS_B + 2 * WS_B)   // 59392

__global__ __launch_bounds__(224, 2) void gemm_xproj() {
    extern __shared__ char smraw[];
    float* xs_base = (float*)smraw;                  // [2][KT][MT]
    u64*   ws_base = (u64*)(smraw + 2 * XS_B);       // [2][KT][GDIM]
    const int tid = threadIdx.x;
    const int gr0 = blockIdx.x * MT;
    const int tm = tid & 7;
    const int tn = tid >> 3;
    const bool active = (tid < 200);

    u64 acc[4][8];
#pragma unroll
    for (int p = 0; p < 4; p++)
#pragma unroll
        for (int j = 0; j < 8; j++) acc[p][j] = 0ull;

    auto issue_tile = [&](int kb, int buf) {
        float* xsb = xs_base + buf * (KT * MT);
        u64*   wsb = ws_base + buf * (KT * GDIM);
        {
            int k = tid >> 4, c = tid & 15;
            cp16(&xsb[k * MT + c * 4], &g_xT[(size_t)(kb + k) * BT + gr0 + c * 4]);
            if (tid < 32) {
                int idx = tid + 224, k2 = idx >> 4, c2 = idx & 15;
                cp16(&xsb[k2 * MT + c2 * 4], &g_xT[(size_t)(kb + k2) * BT + gr0 + c2 * 4]);
            }
        }
        {
#pragma unroll
            for (int u = 0; u < 7; u++) {
                int idx = tid + u * 224;
                int k = idx / 100, cc = idx % 100;
                cp16(&wsb[k * GDIM + cc * 2], &g_Wt2[(kb + k) * GDIM + cc * 2]);
            }
            if (tid < 32) {
                int idx = tid + 7 * 224;
                int k = idx / 100, cc = idx % 100;
                cp16(&wsb[k * GDIM + cc * 2], &g_Wt2[(kb + k) * GDIM + cc * 2]);
            }
        }
        asm volatile("cp.async.commit_group;\n" ::: "memory");
    };

    issue_tile(0, 0);
    int buf = 0;
    const int NTILES = IDIM / KT;
    for (int it = 0; it < NTILES; it++) {
        asm volatile("cp.async.wait_group 0;\n" ::: "memory");
        __syncthreads();
        if (it + 1 < NTILES) issue_tile((it + 1) * KT, buf ^ 1);

        const float* xsb = xs_base + buf * (KT * MT);
        const u64*   wsb = ws_base + buf * (KT * GDIM);
        if (active) {
#pragma unroll
            for (int k = 0; k < KT; k++) {
                ulonglong2 xa = *(const ulonglong2*)&xsb[k * MT + tm * 8];
                ulonglong2 xb = *(const ulonglong2*)&xsb[k * MT + tm * 8 + 4];
                u64 xp2[4] = {xa.x, xa.y, xb.x, xb.y};
                ulonglong2 w0 = *(const ulonglong2*)&wsb[k * GDIM + tn * 8];
                ulonglong2 w1 = *(const ulonglong2*)&wsb[k * GDIM + tn * 8 + 2];
                ulonglong2 w2 = *(const ulonglong2*)&wsb[k * GDIM + tn * 8 + 4];
                ulonglong2 w3 = *(const ulonglong2*)&wsb[k * GDIM + tn * 8 + 6];
                u64 wv[8] = {w0.x, w0.y, w1.x, w1.y, w2.x, w2.y, w3.x, w3.y};
#pragma unroll
                for (int p = 0; p < 4; p++)
#pragma unroll
                    for (int j = 0; j < 8; j++)
                        acc[p][j] = ffma2(xp2[p], wv[j], acc[p][j]);
            }
        }
        __syncthreads();
        buf ^= 1;
    }

    if (active) {
        float bv[8];
#pragma unroll
        for (int j = 0; j < 8; j++) bv[j] = g_bias[tn * 8 + j];
#pragma unroll
        for (int p = 0; p < 4; p++) {
            float r0[8], r1[8];
#pragma unroll
            for (int j = 0; j < 8; j++) {
                float a, b;
                up2(acc[p][j], a, b);
                r0[j] = a + bv[j];
                r1[j] = b + bv[j];
            }
            int row0 = gr0 + tm * 8 + 2 * p;
            float* o0 = &g_xp[(size_t)row0 * GDIM + tn * 8];
            float* o1 = o0 + GDIM;
            *(float4*)o0       = make_float4(r0[0], r0[1], r0[2], r0[3]);
            *(float4*)(o0 + 4) = make_float4(r0[4], r0[5], r0[6], r0[7]);
            *(float4*)o1       = make_float4(r1[0], r1[1], r1[2], r1[3]);
            *(float4*)(o1 + 4) = make_float4(r1[4], r1[5], r1[6], r1[7]);
        }
    }
}

// ============================================================
// Kernel 3: LSTM recurrence + FC head. R3 shape (2 batches/block,
// grid 256, W_hh dup-pairs in registers) + cp.async CHUNK pipeline
// for x_proj: 8 timesteps x 2 batches staged into SMEM, issued two
// chunks ahead -> DRAM latency fully hidden.
// ============================================================
#define CHUNK 8
#define CGF (CHUNK * GDIM)     // floats per batch per chunk = 1600

__global__ __launch_bounds__(224, 2) void lstm_rec(
    const float* __restrict__ W_hh, const float* __restrict__ W_fc,
    const float* __restrict__ b_fc, float* __restrict__ out)
{
    __shared__ alignas(16) float2 h_sh[HDIM];
    __shared__ alignas(16) float2 gate_sh[GDIM];
    __shared__ alignas(16) float xbuf[2][2][CGF];   // [buf][batch][t*200+g], 25.6KB

    const int b0 = blockIdx.x * 2;
    const int g = threadIdx.x;
    const bool gate_active = (g < GDIM);

    u64 w2[HDIM];
    if (gate_active) {
#pragma unroll
        for (int j = 0; j < HDIM; j++) {
            float w = W_hh[g * HDIM + j];
            w2[j] = pk2(w, w);
        }
    }
    if (g < HDIM) h_sh[g] = make_float2(0.f, 0.f);
    float c0 = 0.f, c1 = 0.f;

    const float* xp0 = g_xp + (size_t)b0 * (TLEN * GDIM);
    const float* xp1 = xp0 + (size_t)(TLEN * GDIM);
    const bool isg = (g >= 2 * HDIM && g < 3 * HDIM);   // tanh gate

    auto issue_chunk = [&](int buf, int t0) {
        // 2 batches x 400 16B-chunks, coalesced
        for (int idx = g; idx < 2 * (CGF / 4); idx += 224) {
            int b = idx / (CGF / 4);
            int r = idx - b * (CGF / 4);
            const float* src = (b ? xp1 : xp0) + t0 * GDIM + r * 4;
            cp16(&xbuf[buf][b][r * 4], src);
        }
        asm volatile("cp.async.commit_group;\n" ::: "memory");
    };

    issue_chunk(0, 0);
    issue_chunk(1, CHUNK);

    int cur = 0;
    for (int t0 = 0; t0 < TLEN; t0 += CHUNK) {
        if (t0 + CHUNK < TLEN)
            asm volatile("cp.async.wait_group 1;\n" ::: "memory");
        else
            asm volatile("cp.async.wait_group 0;\n" ::: "memory");
        __syncthreads();   // chunk visible (also covers h_sh init on iter 0)

        const float* xb0 = xbuf[cur][0];
        const float* xb1 = xbuf[cur][1];
#pragma unroll
        for (int tt = 0; tt < CHUNK; tt++) {
            if (gate_active) {
                float x0 = xb0[tt * GDIM + g];
                float x1 = xb1[tt * GDIM + g];
                u64 accA = pk2(x0, x1);
                u64 accB = 0ull;
#pragma unroll
                for (int j = 0; j < HDIM; j += 2) {
                    ulonglong2 hv = *(const ulonglong2*)(h_sh + j);
                    accA = ffma2(hv.x, w2[j],     accA);
                    accB = ffma2(hv.y, w2[j + 1], accB);
                }
                float a0, a1;
                up2(fadd2(accA, accB), a0, a1);
                float z0 = isg ? (a0 + a0) : a0;
                float z1 = isg ? (a1 + a1) : a1;
                float s0 = fast_sigmoid(z0);
                float s1 = fast_sigmoid(z1);
                float r0 = isg ? (2.f * s0 - 1.f) : s0;
                float r1 = isg ? (2.f * s1 - 1.f) : s1;
                gate_sh[g] = make_float2(r0, r1);
            }
            __syncthreads();
            if (g < HDIM) {
                float2 iv = gate_sh[g];
                float2 fv = gate_sh[g + HDIM];
                float2 gv = gate_sh[g + 2 * HDIM];
                float2 ov = gate_sh[g + 3 * HDIM];
                c0 = fmaf(fv.x, c0, iv.x * gv.x);
                c1 = fmaf(fv.y, c1, iv.y * gv.y);
                float th0 = 2.f * fast_sigmoid(c0 + c0) - 1.f;
                float th1 = 2.f * fast_sigmoid(c1 + c1) - 1.f;
                h_sh[g] = make_float2(ov.x * th0, ov.y * th1);
            }
            __syncthreads();
        }

        // refill the buffer we just finished reading (all reads are behind
        // the trailing __syncthreads of step tt=7)
        if (t0 + 2 * CHUNK < TLEN) issue_chunk(cur, t0 + 2 * CHUNK);
        cur ^= 1;
    }

    // FC head for both batches
    if (g < ODIM) {
        float a0 = b_fc[g], a1 = a0;
#pragma unroll
        for (int j = 0; j < HDIM; j++) {
            float2 h = h_sh[j];
            float w = W_fc[g * HDIM + j];
            a0 = fmaf(h.x, w, a0);
            a1 = fmaf(h.y, w, a1);
        }
        out[b0 * ODIM + g]       = a0;
        out[(b0 + 1) * ODIM + g] = a1;
    }
}

// ============================================================
// Launch
// ============================================================
extern "C" void kernel_launch(void* const* d_in, const int* in_sizes, int n_in,
                              void* d_out, int out_size) {
    const float* x    = (const float*)d_in[0];
    const float* W_ih = (const float*)d_in[1];
    const float* W_hh = (const float*)d_in[2];
    const float* b_ih = (const float*)d_in[3];
    const float* b_hh = (const float*)d_in[4];
    const float* W_fc = (const float*)d_in[5];
    const float* b_fc = (const float*)d_in[6];
    float* out = (float*)d_out;

    cudaFuncSetAttribute(gemm_xproj, cudaFuncAttributeMaxDynamicSharedMemorySize,
                         GEMM_SMEM);

    prep_w<<<32, 256>>>(W_ih, b_ih, b_hh);
    transpose_x<<<dim3(BT / 32, IDIM / 32), dim3(32, 8)>>>(x);
    gemm_xproj<<<BT / MT, 224, GEMM_SMEM>>>();
    lstm_rec<<<BSZ / 2, 224>>>(W_hh, W_fc, b_fc, out);
}

// round 9
// speedup vs baseline: 2.5409x; 1.5412x over previous
#include <cuda_runtime.h>
#include <cuda_bf16.h>
#include <cstdint>

#define BSZ  512
#define TLEN 512
#define IDIM 128
#define HDIM 50
#define ODIM 10
#define GDIM 200              // 4*H
#define BT   (BSZ * TLEN)     // 262144 rows

typedef unsigned long long u64;
typedef unsigned int u32;

// ---- scratch (device globals; no allocation allowed) ----
__device__ u32   g_Bimg[102400 / 4];   // W bf16 hi/lo, mma-fragment-ordered
__device__ float g_bias[GDIM];         // b_ih + b_hh
__device__ float g_xp[BT * GDIM];      // x_proj: [row][g]

// ---- packed f32x2 helpers (lstm) ----
__device__ __forceinline__ u64 pk2(float lo, float hi) {
    u64 d;
    asm("mov.b64 %0, {%1, %2};" : "=l"(d) : "f"(lo), "f"(hi));
    return d;
}
__device__ __forceinline__ void up2(u64 v, float& lo, float& hi) {
    asm("mov.b64 {%0, %1}, %2;" : "=f"(lo), "=f"(hi) : "l"(v));
}
__device__ __forceinline__ u64 ffma2(u64 a, u64 b, u64 c) {
    u64 d;
    asm("fma.rn.f32x2 %0, %1, %2, %3;" : "=l"(d) : "l"(a), "l"(b), "l"(c));
    return d;
}
__device__ __forceinline__ u64 fadd2(u64 a, u64 b) {
    u64 d;
    asm("add.rn.f32x2 %0, %1, %2;" : "=l"(d) : "l"(a), "l"(b));
    return d;
}
__device__ __forceinline__ float fast_sigmoid(float x) {
    return 1.f / (1.f + __expf(-x));
}
__device__ __forceinline__ void cp16(void* smem, const void* gmem) {
    unsigned sa = (unsigned)__cvta_generic_to_shared(smem);
    asm volatile("cp.async.cg.shared.global [%0], [%1], 16;\n" :: "r"(sa), "l"(gmem));
}

// hi/lo bf16 split of one float
__device__ __forceinline__ void split_bf16(float v, unsigned short& h, unsigned short& l) {
    __nv_bfloat16 hb = __float2bfloat16_rn(v);
    float lf = v - __bfloat162float(hb);
    __nv_bfloat16 lb = __float2bfloat16_rn(lf);
    h = __bfloat16_as_ushort(hb);
    l = __bfloat16_as_ushort(lb);
}

// mma.sync m16n8k16 row.col f32.bf16.bf16.f32
__device__ __forceinline__ void mma16816(float* c, const u32* a, u32 b0, u32 b1) {
    asm volatile(
        "mma.sync.aligned.m16n8k16.row.col.f32.bf16.bf16.f32 "
        "{%0,%1,%2,%3}, {%4,%5,%6,%7}, {%8,%9}, {%0,%1,%2,%3};"
        : "+f"(c[0]), "+f"(c[1]), "+f"(c[2]), "+f"(c[3])
        : "r"(a[0]), "r"(a[1]), "r"(a[2]), "r"(a[3]), "r"(b0), "r"(b1));
}

// ============================================================
// Kernel 0: build W fragment-ordered bf16 hi/lo image + bias.
// B frag (m16n8k16 col-major B): lane = (n&7)*4 + ((k&7)>>1),
// b0: k<8, b1: k>=8. Per-lane 16B = {b0hi, b1hi, b0lo, b1lo}.
// Image index: ((kc*25 + ntile)*32 + lane)*4 u32 + reg (lo at +2).
// ============================================================
__global__ void prep(const float* __restrict__ W_ih,
                     const float* __restrict__ b_ih,
                     const float* __restrict__ b_hh) {
    int t = threadIdx.x;
    for (int idx = t; idx < GDIM * (IDIM / 2); idx += 256) {
        int g  = idx >> 6;          // / 64 pairs per row
        int k2 = (idx & 63) * 2;
        unsigned short h0, l0, h1, l1;
        split_bf16(W_ih[g * IDIM + k2],     h0, l0);
        split_bf16(W_ih[g * IDIM + k2 + 1], h1, l1);
        u32 hp = (u32)h0 | ((u32)h1 << 16);
        u32 lp = (u32)l0 | ((u32)l1 << 16);
        int nt = g >> 3, nloc = g & 7;
        int kc = k2 >> 4, kloc = k2 & 15;
        int lane = nloc * 4 + ((kloc & 7) >> 1);
        int reg  = kloc >> 3;
        int base = ((kc * 25 + nt) * 32 + lane) * 4;
        g_Bimg[base + reg]     = hp;
        g_Bimg[base + 2 + reg] = lp;
    }
    if (t < GDIM) g_bias[t] = b_ih[t] + b_hh[t];
}

// ============================================================
// Kernel 1: HMMA GEMM, bf16 hi/lo split, fp32 accum.
// Block: 256 thr (8 warps), tile M=128 x N=200 x K=128.
// A stored fragment-ordered in SMEM (hi block + lo block),
// B image cp.async'd whole. 1 sync, no swizzle, no ldmatrix.
// ============================================================
#define SM_AHI  0
#define SM_ALO  32768
#define SM_B    65536            // 102400 B
#define SM_BIAS 167936           // 800 B
#define MMA_SMEM 168960

__global__ __launch_bounds__(256, 1) void gemm_mma(const float* __restrict__ x) {
    extern __shared__ char sm[];
    u32*   aHi  = (u32*)(sm + SM_AHI);
    u32*   aLo  = (u32*)(sm + SM_ALO);
    u32*   bImg = (u32*)(sm + SM_B);
    float* bias = (float*)(sm + SM_BIAS);

    const int tid = threadIdx.x;
    const int w   = tid >> 5;
    const int l   = tid & 31;
    const int row0 = blockIdx.x * 128;

    // B image: 6400 x 16B chunks, 25 per thread (async)
#pragma unroll
    for (int u = 0; u < 25; u++) {
        int idx = tid + u * 256;
        cp16(bImg + idx * 4, g_Bimg + idx * 4);
    }
    asm volatile("cp.async.commit_group;\n" ::: "memory");

    if (tid < GDIM) bias[tid] = g_bias[tid];

    // A: convert x tile (128 rows x 128 k) to bf16 hi/lo fragments.
    // A frag: lane = (r&7)*4 + ((k&7)>>1); reg = (k>=8)*2 + (r>=8).
    // addr u32: ((m*8+kc)*32 + lane)*4 + reg
    // 128 rows x 32 float4-chunks = 4096 chunks = 16 per thread.
#pragma unroll
    for (int i = 0; i < 16; i++) {
        int idx = tid + i * 256;          // 4096 float4 total
        int r  = idx >> 5;
        int k4 = (idx & 31) * 4;
        float4 v = *(const float4*)&x[(size_t)(row0 + r) * IDIM + k4];
#pragma unroll
        for (int p = 0; p < 2; p++) {
            int k2 = k4 + 2 * p;
            float e0 = p ? v.z : v.x;
            float e1 = p ? v.w : v.y;
            unsigned short h0, l0, h1, l1;
            split_bf16(e0, h0, l0);
            split_bf16(e1, h1, l1);
            u32 hp = (u32)h0 | ((u32)h1 << 16);
            u32 lp = (u32)l0 | ((u32)l1 << 16);
            int m = r >> 4, rloc = r & 15;
            int kc = k2 >> 4, kloc = k2 & 15;
            int lane = (rloc & 7) * 4 + ((kloc & 7) >> 1);
            int reg  = (kloc >> 3) * 2 + (rloc >> 3);
            int a4   = ((m * 8 + kc) * 32 + lane) * 4 + reg;
            aHi[a4] = hp;
            aLo[a4] = lp;
        }
    }

    asm volatile("cp.async.wait_group 0;\n" ::: "memory");
    __syncthreads();

    // compute: warp w owns m-tile w. acc[25][4].
    float acc[25][4];
#pragma unroll
    for (int n = 0; n < 25; n++)
#pragma unroll
        for (int j = 0; j < 4; j++) acc[n][j] = 0.f;

#pragma unroll
    for (int kc = 0; kc < 8; kc++) {
        uint4 ah = *(const uint4*)&aHi[((w * 8 + kc) * 32 + l) * 4];
        uint4 al = *(const uint4*)&aLo[((w * 8 + kc) * 32 + l) * 4];
        u32 ahr[4] = {ah.x, ah.y, ah.z, ah.w};
        u32 alr[4] = {al.x, al.y, al.z, al.w};
#pragma unroll
        for (int n = 0; n < 25; n++) {
            uint4 b = *(const uint4*)&bImg[((kc * 25 + n) * 32 + l) * 4];
            mma16816(acc[n], ahr, b.x, b.y);   // hi * hi
            mma16816(acc[n], ahr, b.z, b.w);   // hi * lo
            mma16816(acc[n], alr, b.x, b.y);   // lo * hi
        }
    }

    // epilogue: D frag c0/c1: row=l>>2, col=(l&3)*2 (+1); c2/c3: row+8.
    {
        int r0 = row0 + w * 16 + (l >> 2);
        int r1 = r0 + 8;
#pragma unroll
        for (int n = 0; n < 25; n++) {
            int c = n * 8 + (l & 3) * 2;
            float2 bv = *(const float2*)&bias[c];
            float2 o0 = make_float2(acc[n][0] + bv.x, acc[n][1] + bv.y);
            float2 o1 = make_float2(acc[n][2] + bv.x, acc[n][3] + bv.y);
            *(float2*)&g_xp[(size_t)r0 * GDIM + c] = o0;
            *(float2*)&g_xp[(size_t)r1 * GDIM + c] = o1;
        }
    }
}

// ============================================================
// Kernel 2: LSTM recurrence + FC head (R3 version, measured 361us).
// 2 batches/block, grid 256, W_hh dup-pairs in registers.
// ============================================================
__global__ __launch_bounds__(224, 2) void lstm_rec(
    const float* __restrict__ W_hh, const float* __restrict__ W_fc,
    const float* __restrict__ b_fc, float* __restrict__ out)
{
    __shared__ alignas(16) float2 h_sh[HDIM];
    __shared__ alignas(16) float2 gate_sh[GDIM];
    const int b0 = blockIdx.x * 2;
    const int g = threadIdx.x;

    u64 w2[HDIM];
    if (g < GDIM) {
#pragma unroll
        for (int j = 0; j < HDIM; j++) {
            float w = W_hh[g * HDIM + j];
            w2[j] = pk2(w, w);
        }
    }
    if (g < HDIM) h_sh[g] = make_float2(0.f, 0.f);
    float c0 = 0.f, c1 = 0.f;

    const float* xp0 = g_xp + (size_t)b0 * (TLEN * GDIM);
    const float* xp1 = xp0 + (size_t)(TLEN * GDIM);
    float xc0 = 0.f, xc1 = 0.f;
    if (g < GDIM) { xc0 = xp0[g]; xc1 = xp1[g]; }
    const bool isg = (g >= 2 * HDIM && g < 3 * HDIM);   // tanh gate
    __syncthreads();

    for (int t = 0; t < TLEN; t++) {
        if (g < GDIM) {
            u64 accA = pk2(xc0, xc1);
            u64 accB = 0ull;
            if (t + 1 < TLEN) {                          // prefetch next step
                xc0 = xp0[(t + 1) * GDIM + g];
                xc1 = xp1[(t + 1) * GDIM + g];
            }
#pragma unroll
            for (int j = 0; j < HDIM; j += 2) {
                ulonglong2 hv = *(const ulonglong2*)(h_sh + j);
                accA = ffma2(hv.x, w2[j],     accA);
                accB = ffma2(hv.y, w2[j + 1], accB);
            }
            float a0, a1;
            up2(fadd2(accA, accB), a0, a1);
            float z0 = isg ? (a0 + a0) : a0;
            float z1 = isg ? (a1 + a1) : a1;
            float s0 = fast_sigmoid(z0);
            float s1 = fast_sigmoid(z1);
            float r0 = isg ? (2.f * s0 - 1.f) : s0;
            float r1 = isg ? (2.f * s1 - 1.f) : s1;
            gate_sh[g] = make_float2(r0, r1);
        }
        __syncthreads();
        if (g < HDIM) {
            float2 iv = gate_sh[g];
            float2 fv = gate_sh[g + HDIM];
            float2 gv = gate_sh[g + 2 * HDIM];
            float2 ov = gate_sh[g + 3 * HDIM];
            c0 = fmaf(fv.x, c0, iv.x * gv.x);
            c1 = fmaf(fv.y, c1, iv.y * gv.y);
            float th0 = 2.f * fast_sigmoid(c0 + c0) - 1.f;
            float th1 = 2.f * fast_sigmoid(c1 + c1) - 1.f;
            h_sh[g] = make_float2(ov.x * th0, ov.y * th1);
        }
        __syncthreads();
    }

    // FC head for both batches
    if (g < ODIM) {
        float a0 = b_fc[g], a1 = a0;
#pragma unroll
        for (int j = 0; j < HDIM; j++) {
            float2 h = h_sh[j];
            float w = W_fc[g * HDIM + j];
            a0 = fmaf(h.x, w, a0);
            a1 = fmaf(h.y, w, a1);
        }
        out[b0 * ODIM + g]       = a0;
        out[(b0 + 1) * ODIM + g] = a1;
    }
}

// ============================================================
// Launch
// ============================================================
extern "C" void kernel_launch(void* const* d_in, const int* in_sizes, int n_in,
                              void* d_out, int out_size) {
    const float* x    = (const float*)d_in[0];
    const float* W_ih = (const float*)d_in[1];
    const float* W_hh = (const float*)d_in[2];
    const float* b_ih = (const float*)d_in[3];
    const float* b_hh = (const float*)d_in[4];
    const float* W_fc = (const float*)d_in[5];
    const float* b_fc = (const float*)d_in[6];
    float* out = (float*)d_out;

    cudaFuncSetAttribute(gemm_mma, cudaFuncAttributeMaxDynamicSharedMemorySize,
                         MMA_SMEM);

    prep<<<1, 256>>>(W_ih, b_ih, b_hh);
    gemm_mma<<<BT / 128, 256, MMA_SMEM>>>(x);
    lstm_rec<<<BSZ / 2, 224>>>(W_hh, W_fc, b_fc, out);
}